// round 4
// baseline (speedup 1.0000x reference)
#include <cuda_runtime.h>
#include <cuda_bf16.h>
#include <math.h>
#include <stdint.h>

// Problem constants (VectorizedMoE: B=16384, H=1024, E=8, K=2)
#define B_TOK 16384
#define H_DIM 1024
#define N_EXP 8

#define BM 128
#define BN 128
#define KT 32                   // k elems per smem stage
#define KTP 40                  // padded row length (elems) -> 80B rows, conflict-free ldmatrix
#define N_KTILES (H_DIM / KT)   // 32
#define TENSOR_B (BM * KTP * 2) // 10240 bytes per operand tile
#define STAGE_B (4 * TENSOR_B)  // Ah, Al, Bh, Bl
#define DSMEM_BYTES (2 * STAGE_B)

// ---------------------------------------------------------------------------
// Scratch (static __device__ — no allocations allowed).
// ---------------------------------------------------------------------------
__device__ int   g_cnt[N_EXP];
__device__ int   g_tok[N_EXP * B_TOK];
__device__ float g_w  [N_EXP * B_TOK];

__device__ __align__(256) __nv_bfloat16 g_x_hi[B_TOK * H_DIM];
__device__ __align__(256) __nv_bfloat16 g_x_lo[B_TOK * H_DIM];
__device__ __align__(256) __nv_bfloat16 g_WeT_hi[(size_t)N_EXP * H_DIM * H_DIM]; // [e][n][k]
__device__ __align__(256) __nv_bfloat16 g_WeT_lo[(size_t)N_EXP * H_DIM * H_DIM];

// ---------------------------------------------------------------------------
// PTX helpers (sm_100-plain safe: cp.async / ldmatrix / mma.sync only)
// ---------------------------------------------------------------------------
__device__ __forceinline__ uint32_t smem_u32(const void* p) {
    uint32_t a;
    asm("{ .reg .u64 t; cvta.to.shared.u64 t, %1; cvt.u32.u64 %0, t; }"
        : "=r"(a) : "l"(p));
    return a;
}
#define CP_ASYNC16(s, g) \
    asm volatile("cp.async.cg.shared.global [%0], [%1], 16;" :: "r"(s), "l"(g))
#define CP_COMMIT() asm volatile("cp.async.commit_group;" ::: "memory")
#define CP_WAIT(N)  asm volatile("cp.async.wait_group %0;" :: "n"(N) : "memory")

__device__ __forceinline__ void ldm4(uint32_t* r, uint32_t addr) {
    asm volatile("ldmatrix.sync.aligned.m8n8.x4.shared.b16 {%0,%1,%2,%3}, [%4];"
                 : "=r"(r[0]), "=r"(r[1]), "=r"(r[2]), "=r"(r[3]) : "r"(addr));
}
__device__ __forceinline__ void mma16816(float* c, const uint32_t* a, uint32_t b0, uint32_t b1) {
    asm volatile(
        "mma.sync.aligned.m16n8k16.row.col.f32.bf16.bf16.f32 "
        "{%0,%1,%2,%3}, {%4,%5,%6,%7}, {%8,%9}, {%0,%1,%2,%3};"
        : "+f"(c[0]), "+f"(c[1]), "+f"(c[2]), "+f"(c[3])
        : "r"(a[0]), "r"(a[1]), "r"(a[2]), "r"(a[3]), "r"(b0), "r"(b1));
}

// ---------------------------------------------------------------------------
// 1) init
// ---------------------------------------------------------------------------
__global__ void init_kernel(float* __restrict__ out, int n) {
    int i = blockIdx.x * blockDim.x + threadIdx.x;
    if (i < N_EXP) g_cnt[i] = 0;
    int stride = gridDim.x * blockDim.x;
    for (int j = i; j < n; j += stride) out[j] = 0.0f;
}

// ---------------------------------------------------------------------------
// 2) convert x -> hi/lo bf16
// ---------------------------------------------------------------------------
__global__ void conv_x_kernel(const float* __restrict__ x) {
    int n4 = (B_TOK * H_DIM) / 4;
    int stride = gridDim.x * blockDim.x;
    for (int i = blockIdx.x * blockDim.x + threadIdx.x; i < n4; i += stride) {
        float4 v = ((const float4*)x)[i];
        __nv_bfloat16 h0 = __float2bfloat16(v.x);
        __nv_bfloat16 h1 = __float2bfloat16(v.y);
        __nv_bfloat16 h2 = __float2bfloat16(v.z);
        __nv_bfloat16 h3 = __float2bfloat16(v.w);
        __nv_bfloat16 l0 = __float2bfloat16(v.x - __bfloat162float(h0));
        __nv_bfloat16 l1 = __float2bfloat16(v.y - __bfloat162float(h1));
        __nv_bfloat16 l2 = __float2bfloat16(v.z - __bfloat162float(h2));
        __nv_bfloat16 l3 = __float2bfloat16(v.w - __bfloat162float(h3));
        __nv_bfloat162* ph = (__nv_bfloat162*)g_x_hi;
        __nv_bfloat162* pl = (__nv_bfloat162*)g_x_lo;
        ph[i * 2]     = __nv_bfloat162(h0, h1);
        ph[i * 2 + 1] = __nv_bfloat162(h2, h3);
        pl[i * 2]     = __nv_bfloat162(l0, l1);
        pl[i * 2 + 1] = __nv_bfloat162(l2, l3);
    }
}

// ---------------------------------------------------------------------------
// 3) convert + transpose We[e][k][n] -> WeT[e][n][k] hi/lo bf16
// ---------------------------------------------------------------------------
__global__ void conv_weT_kernel(const float* __restrict__ We) {
    __shared__ float tile[32][33];
    int e  = blockIdx.z;
    int n0 = blockIdx.x * 32;
    int k0 = blockIdx.y * 32;
    int tx = threadIdx.x, ty = threadIdx.y;
#pragma unroll
    for (int j = 0; j < 4; j++) {
        int k = k0 + ty + j * 8;
        tile[ty + j * 8][tx] = We[((size_t)e * H_DIM + k) * H_DIM + n0 + tx];
    }
    __syncthreads();
#pragma unroll
    for (int j = 0; j < 4; j++) {
        int n = n0 + ty + j * 8;
        int k = k0 + tx;
        float v = tile[tx][ty + j * 8];
        __nv_bfloat16 hi = __float2bfloat16(v);
        __nv_bfloat16 lo = __float2bfloat16(v - __bfloat162float(hi));
        size_t o = ((size_t)e * H_DIM + n) * H_DIM + k;
        g_WeT_hi[o] = hi;
        g_WeT_lo[o] = lo;
    }
}

// ---------------------------------------------------------------------------
// 4) gate (verified in R1)
// ---------------------------------------------------------------------------
__global__ void gate_kernel(const float* __restrict__ x,
                            const float* __restrict__ Wg,
                            const float* __restrict__ bg) {
    int warp = threadIdx.x >> 5;
    int lane = threadIdx.x & 31;
    int b = blockIdx.x * 8 + warp;
    if (b >= B_TOK) return;

    const float* xr = x + (size_t)b * H_DIM;
    float acc[N_EXP];
#pragma unroll
    for (int e = 0; e < N_EXP; e++) acc[e] = 0.0f;
    for (int h = lane; h < H_DIM; h += 32) {
        float xv = xr[h];
        const float* wr = Wg + (size_t)h * N_EXP;
#pragma unroll
        for (int e = 0; e < N_EXP; e++) acc[e] = fmaf(xv, wr[e], acc[e]);
    }
#pragma unroll
    for (int off = 16; off > 0; off >>= 1) {
#pragma unroll
        for (int e = 0; e < N_EXP; e++)
            acc[e] += __shfl_xor_sync(0xffffffffu, acc[e], off);
    }
    if (lane == 0) {
#pragma unroll
        for (int e = 0; e < N_EXP; e++) acc[e] += bg[e];
        int e0 = 0; float v0 = acc[0];
        int e1 = -1; float v1 = -3.4e38f;
#pragma unroll
        for (int e = 1; e < N_EXP; e++) {
            float v = acc[e];
            if (v > v0)      { v1 = v0; e1 = e0; v0 = v; e0 = e; }
            else if (v > v1) { v1 = v;  e1 = e; }
        }
        float t  = expf(v1 - v0);
        float s  = 1.0f + t;
        float w0 = 1.0f / s;
        float w1 = t / s;
        int s0 = atomicAdd(&g_cnt[e0], 1);
        g_tok[e0 * B_TOK + s0] = b;
        g_w  [e0 * B_TOK + s0] = w0;
        int s1 = atomicAdd(&g_cnt[e1], 1);
        g_tok[e1 * B_TOK + s1] = b;
        g_w  [e1 * B_TOK + s1] = w1;
    }
}

// ---------------------------------------------------------------------------
// 5) grouped GEMM: mma.sync bf16 split-3, cp.async 2-stage pipeline.
//    512 threads, 4x4 warp grid, 32x32 warp tile.
// ---------------------------------------------------------------------------
__global__ __launch_bounds__(512, 1)
void moe_mma_kernel(const float* __restrict__ be, float* __restrict__ out) {
    int e    = blockIdx.z;
    int M    = g_cnt[e];
    int row0 = blockIdx.y * BM;
    if (row0 >= M) return;
    int col0 = blockIdx.x * BN;

    int tid  = threadIdx.x;
    int wid  = tid >> 5;
    int lane = tid & 31;
    int wm   = wid >> 2;    // 0..3  (m)
    int wn   = wid & 3;     // 0..3  (n)

    __shared__ int   s_tok[BM];
    __shared__ float s_w[BM];
    extern __shared__ char dsm[];
    uint32_t sbase = smem_u32(dsm);

    if (tid < BM) {
        int r = row0 + tid;
        if (r < M) {
            s_tok[tid] = g_tok[e * B_TOK + r];
            s_w[tid]   = g_w  [e * B_TOK + r];
        } else {
            s_tok[tid] = 0;
            s_w[tid]   = 0.0f;
        }
    }
    __syncthreads();

    const __nv_bfloat16* WeTh = g_WeT_hi + (size_t)e * H_DIM * H_DIM;
    const __nv_bfloat16* WeTl = g_WeT_lo + (size_t)e * H_DIM * H_DIM;

    // per-thread load slots: one 16B chunk per tensor per stage
    int lr = tid >> 2;          // 0..127 (row)
    int lc = tid & 3;           // 0..3   (16B chunk within 64B of k-tile)
    uint32_t s_off = (uint32_t)(lr * (KTP * 2) + lc * 16);
    size_t   a_go  = (size_t)s_tok[lr] * H_DIM + lc * 8;
    size_t   b_go  = (size_t)(col0 + lr) * H_DIM + lc * 8;

    // issue loads for k-tile t into stage st
    auto load_stage = [&](int t, int st) {
        uint32_t sb = sbase + st * STAGE_B + s_off;
        int k0 = t * KT;
        CP_ASYNC16(sb + 0 * TENSOR_B, (const char*)(g_x_hi + a_go + k0));
        CP_ASYNC16(sb + 1 * TENSOR_B, (const char*)(g_x_lo + a_go + k0));
        CP_ASYNC16(sb + 2 * TENSOR_B, (const char*)(WeTh + b_go + k0));
        CP_ASYNC16(sb + 3 * TENSOR_B, (const char*)(WeTl + b_go + k0));
        CP_COMMIT();
    };

    float acc[2][4][4];
#pragma unroll
    for (int mi = 0; mi < 2; mi++)
#pragma unroll
        for (int ni = 0; ni < 4; ni++)
#pragma unroll
            for (int j = 0; j < 4; j++) acc[mi][ni][j] = 0.0f;

    // ldmatrix lane-address components
    int aRow = (lane & 7) + ((lane >> 3) & 1) * 8;  // A: tiles {m, m+8, k, k+8}
    int aKb  = ((lane >> 4) & 1) * 16;
    int bRow = (lane & 7) + ((lane >> 4) & 1) * 8;  // B: tiles {k, k+8, n+8...}
    int bKb  = ((lane >> 3) & 1) * 16;

    load_stage(0, 0);

    for (int t = 0; t < N_KTILES; t++) {
        int st = t & 1;
        if (t + 1 < N_KTILES) {
            load_stage(t + 1, st ^ 1);
            CP_WAIT(1);
        } else {
            CP_WAIT(0);
        }
        __syncthreads();

        uint32_t sA = sbase + st * STAGE_B;
        uint32_t sB = sA + 2 * TENSOR_B;

#pragma unroll
        for (int ks = 0; ks < 2; ks++) {
            int kb = ks * 32;  // 16 elems * 2B
            uint32_t ah[2][4], al[2][4], bh[2][4], bl[2][4];
#pragma unroll
            for (int mi = 0; mi < 2; mi++) {
                uint32_t ra = (uint32_t)((wm * 32 + mi * 16 + aRow) * (KTP * 2) + kb + aKb);
                ldm4(ah[mi], sA + 0 * TENSOR_B + ra);
                ldm4(al[mi], sA + 1 * TENSOR_B + ra);
            }
#pragma unroll
            for (int np = 0; np < 2; np++) {
                uint32_t rb = (uint32_t)((wn * 32 + np * 16 + bRow) * (KTP * 2) + kb + bKb);
                ldm4(bh[np], sB + 0 * TENSOR_B + rb);
                ldm4(bl[np], sB + 1 * TENSOR_B + rb);
            }
#pragma unroll
            for (int mi = 0; mi < 2; mi++) {
#pragma unroll
                for (int ni = 0; ni < 4; ni++) {
                    uint32_t b0h = bh[ni >> 1][(ni & 1) * 2];
                    uint32_t b1h = bh[ni >> 1][(ni & 1) * 2 + 1];
                    uint32_t b0l = bl[ni >> 1][(ni & 1) * 2];
                    uint32_t b1l = bl[ni >> 1][(ni & 1) * 2 + 1];
                    mma16816(acc[mi][ni], ah[mi], b0h, b1h);
                    mma16816(acc[mi][ni], ah[mi], b0l, b1l);
                    mma16816(acc[mi][ni], al[mi], b0h, b1h);
                }
            }
        }
        __syncthreads();
    }

    // epilogue: weighted atomic scatter-add with bias
    const float* bep = be + (size_t)e * H_DIM + col0 + wn * 32;
#pragma unroll
    for (int mi = 0; mi < 2; mi++) {
        int g = wm * 32 + mi * 16 + (lane >> 2);
#pragma unroll
        for (int h = 0; h < 2; h++) {
            int rr = g + h * 8;
            if (row0 + rr < M) {
                float w   = s_w[rr];
                float* op = out + (size_t)s_tok[rr] * H_DIM + col0 + wn * 32;
#pragma unroll
                for (int ni = 0; ni < 4; ni++) {
                    int c = ni * 8 + (lane & 3) * 2;
                    float b0 = __ldg(bep + c);
                    float b1 = __ldg(bep + c + 1);
                    atomicAdd(op + c,     w * (acc[mi][ni][h * 2]     + b0));
                    atomicAdd(op + c + 1, w * (acc[mi][ni][h * 2 + 1] + b1));
                }
            }
        }
    }
}

// ---------------------------------------------------------------------------
// launch
// ---------------------------------------------------------------------------
extern "C" void kernel_launch(void* const* d_in, const int* in_sizes, int n_in,
                              void* d_out, int out_size) {
    const float* x  = (const float*)d_in[0];   // [B, H]
    const float* Wg = (const float*)d_in[1];   // [H, E]
    const float* bg = (const float*)d_in[2];   // [E]
    const float* We = (const float*)d_in[3];   // [E, H, H]
    const float* be = (const float*)d_in[4];   // [E, H]
    float* out = (float*)d_out;                // [B, H]

    cudaFuncSetAttribute(moe_mma_kernel,
                         cudaFuncAttributeMaxDynamicSharedMemorySize, DSMEM_BYTES);

    init_kernel<<<1024, 256>>>(out, out_size);
    conv_x_kernel<<<4096, 256>>>(x);
    {
        dim3 grid(H_DIM / 32, H_DIM / 32, N_EXP);
        conv_weT_kernel<<<grid, dim3(32, 8)>>>(We);
    }
    gate_kernel<<<B_TOK / 8, 256>>>(x, Wg, bg);

    dim3 grid(H_DIM / BN, B_TOK / BM, N_EXP);
    moe_mma_kernel<<<grid, 512, DSMEM_BYTES>>>(be, out);
}

// round 5
// speedup vs baseline: 1.0023x; 1.0023x over previous
#include <cuda_runtime.h>
#include <cuda_bf16.h>
#include <math.h>
#include <stdint.h>

// Problem constants (VectorizedMoE: B=16384, H=1024, E=8, K=2)
#define B_TOK 16384
#define H_DIM 1024
#define N_EXP 8

#define BM 128
#define BN 128
#define KT 32                   // k elems per smem stage
#define KTP 40                  // padded row length (elems) -> 80B rows, conflict-free ldmatrix
#define N_KTILES (H_DIM / KT)   // 32
#define TENSOR_B (BM * KTP * 2) // 10240 bytes per operand tile
#define STAGE_B (4 * TENSOR_B)  // Ah, Al, Bh, Bl
#define DSMEM_BYTES (2 * STAGE_B)

// ---------------------------------------------------------------------------
// Scratch (static __device__ — no allocations allowed).
// ---------------------------------------------------------------------------
__device__ int   g_cnt[N_EXP];
__device__ int   g_tok[N_EXP * B_TOK];
__device__ float g_w  [N_EXP * B_TOK];

__device__ __align__(256) __nv_bfloat16 g_x_hi[B_TOK * H_DIM];
__device__ __align__(256) __nv_bfloat16 g_x_lo[B_TOK * H_DIM];
__device__ __align__(256) __nv_bfloat16 g_WeT_hi[(size_t)N_EXP * H_DIM * H_DIM]; // [e][n][k]
__device__ __align__(256) __nv_bfloat16 g_WeT_lo[(size_t)N_EXP * H_DIM * H_DIM];

// ---------------------------------------------------------------------------
// PTX helpers (sm_100-plain safe: cp.async / ldmatrix / mma.sync only)
// ---------------------------------------------------------------------------
__device__ __forceinline__ uint32_t smem_u32(const void* p) {
    uint32_t a;
    asm("{ .reg .u64 t; cvta.to.shared.u64 t, %1; cvt.u32.u64 %0, t; }"
        : "=r"(a) : "l"(p));
    return a;
}
#define CP_ASYNC16(s, g) \
    asm volatile("cp.async.cg.shared.global [%0], [%1], 16;" :: "r"(s), "l"(g))
#define CP_COMMIT() asm volatile("cp.async.commit_group;" ::: "memory")
#define CP_WAIT(N)  asm volatile("cp.async.wait_group %0;" :: "n"(N) : "memory")

__device__ __forceinline__ void ldm4(uint32_t* r, uint32_t addr) {
    asm volatile("ldmatrix.sync.aligned.m8n8.x4.shared.b16 {%0,%1,%2,%3}, [%4];"
                 : "=r"(r[0]), "=r"(r[1]), "=r"(r[2]), "=r"(r[3]) : "r"(addr));
}
__device__ __forceinline__ void mma16816(float* c, const uint32_t* a, uint32_t b0, uint32_t b1) {
    asm volatile(
        "mma.sync.aligned.m16n8k16.row.col.f32.bf16.bf16.f32 "
        "{%0,%1,%2,%3}, {%4,%5,%6,%7}, {%8,%9}, {%0,%1,%2,%3};"
        : "+f"(c[0]), "+f"(c[1]), "+f"(c[2]), "+f"(c[3])
        : "r"(a[0]), "r"(a[1]), "r"(a[2]), "r"(a[3]), "r"(b0), "r"(b1));
}

// ---------------------------------------------------------------------------
// 1) init
// ---------------------------------------------------------------------------
__global__ void init_kernel(float* __restrict__ out, int n) {
    int i = blockIdx.x * blockDim.x + threadIdx.x;
    if (i < N_EXP) g_cnt[i] = 0;
    int stride = gridDim.x * blockDim.x;
    for (int j = i; j < n; j += stride) out[j] = 0.0f;
}

// ---------------------------------------------------------------------------
// 2) convert x -> hi/lo bf16
// ---------------------------------------------------------------------------
__global__ void conv_x_kernel(const float* __restrict__ x) {
    int n4 = (B_TOK * H_DIM) / 4;
    int stride = gridDim.x * blockDim.x;
    for (int i = blockIdx.x * blockDim.x + threadIdx.x; i < n4; i += stride) {
        float4 v = ((const float4*)x)[i];
        __nv_bfloat16 h0 = __float2bfloat16(v.x);
        __nv_bfloat16 h1 = __float2bfloat16(v.y);
        __nv_bfloat16 h2 = __float2bfloat16(v.z);
        __nv_bfloat16 h3 = __float2bfloat16(v.w);
        __nv_bfloat16 l0 = __float2bfloat16(v.x - __bfloat162float(h0));
        __nv_bfloat16 l1 = __float2bfloat16(v.y - __bfloat162float(h1));
        __nv_bfloat16 l2 = __float2bfloat16(v.z - __bfloat162float(h2));
        __nv_bfloat16 l3 = __float2bfloat16(v.w - __bfloat162float(h3));
        __nv_bfloat162* ph = (__nv_bfloat162*)g_x_hi;
        __nv_bfloat162* pl = (__nv_bfloat162*)g_x_lo;
        ph[i * 2]     = __nv_bfloat162(h0, h1);
        ph[i * 2 + 1] = __nv_bfloat162(h2, h3);
        pl[i * 2]     = __nv_bfloat162(l0, l1);
        pl[i * 2 + 1] = __nv_bfloat162(l2, l3);
    }
}

// ---------------------------------------------------------------------------
// 3) convert + transpose We[e][k][n] -> WeT[e][n][k] hi/lo bf16
// ---------------------------------------------------------------------------
__global__ void conv_weT_kernel(const float* __restrict__ We) {
    __shared__ float tile[32][33];
    int e  = blockIdx.z;
    int n0 = blockIdx.x * 32;
    int k0 = blockIdx.y * 32;
    int tx = threadIdx.x, ty = threadIdx.y;
#pragma unroll
    for (int j = 0; j < 4; j++) {
        int k = k0 + ty + j * 8;
        tile[ty + j * 8][tx] = We[((size_t)e * H_DIM + k) * H_DIM + n0 + tx];
    }
    __syncthreads();
#pragma unroll
    for (int j = 0; j < 4; j++) {
        int n = n0 + ty + j * 8;
        int k = k0 + tx;
        float v = tile[tx][ty + j * 8];
        __nv_bfloat16 hi = __float2bfloat16(v);
        __nv_bfloat16 lo = __float2bfloat16(v - __bfloat162float(hi));
        size_t o = ((size_t)e * H_DIM + n) * H_DIM + k;
        g_WeT_hi[o] = hi;
        g_WeT_lo[o] = lo;
    }
}

// ---------------------------------------------------------------------------
// 4) gate (verified in R1)
// ---------------------------------------------------------------------------
__global__ void gate_kernel(const float* __restrict__ x,
                            const float* __restrict__ Wg,
                            const float* __restrict__ bg) {
    int warp = threadIdx.x >> 5;
    int lane = threadIdx.x & 31;
    int b = blockIdx.x * 8 + warp;
    if (b >= B_TOK) return;

    const float* xr = x + (size_t)b * H_DIM;
    float acc[N_EXP];
#pragma unroll
    for (int e = 0; e < N_EXP; e++) acc[e] = 0.0f;
    for (int h = lane; h < H_DIM; h += 32) {
        float xv = xr[h];
        const float* wr = Wg + (size_t)h * N_EXP;
#pragma unroll
        for (int e = 0; e < N_EXP; e++) acc[e] = fmaf(xv, wr[e], acc[e]);
    }
#pragma unroll
    for (int off = 16; off > 0; off >>= 1) {
#pragma unroll
        for (int e = 0; e < N_EXP; e++)
            acc[e] += __shfl_xor_sync(0xffffffffu, acc[e], off);
    }
    if (lane == 0) {
#pragma unroll
        for (int e = 0; e < N_EXP; e++) acc[e] += bg[e];
        int e0 = 0; float v0 = acc[0];
        int e1 = -1; float v1 = -3.4e38f;
#pragma unroll
        for (int e = 1; e < N_EXP; e++) {
            float v = acc[e];
            if (v > v0)      { v1 = v0; e1 = e0; v0 = v; e0 = e; }
            else if (v > v1) { v1 = v;  e1 = e; }
        }
        float t  = expf(v1 - v0);
        float s  = 1.0f + t;
        float w0 = 1.0f / s;
        float w1 = t / s;
        int s0 = atomicAdd(&g_cnt[e0], 1);
        g_tok[e0 * B_TOK + s0] = b;
        g_w  [e0 * B_TOK + s0] = w0;
        int s1 = atomicAdd(&g_cnt[e1], 1);
        g_tok[e1 * B_TOK + s1] = b;
        g_w  [e1 * B_TOK + s1] = w1;
    }
}

// ---------------------------------------------------------------------------
// 5) grouped GEMM: mma.sync bf16 split-3, cp.async 2-stage pipeline.
//    512 threads, 4x4 warp grid, 32x32 warp tile.
// ---------------------------------------------------------------------------
__global__ __launch_bounds__(512, 1)
void moe_mma_kernel(const float* __restrict__ be, float* __restrict__ out) {
    int e    = blockIdx.z;
    int M    = g_cnt[e];
    int row0 = blockIdx.y * BM;
    if (row0 >= M) return;
    int col0 = blockIdx.x * BN;

    int tid  = threadIdx.x;
    int wid  = tid >> 5;
    int lane = tid & 31;
    int wm   = wid >> 2;    // 0..3  (m)
    int wn   = wid & 3;     // 0..3  (n)

    __shared__ int   s_tok[BM];
    __shared__ float s_w[BM];
    extern __shared__ char dsm[];
    uint32_t sbase = smem_u32(dsm);

    if (tid < BM) {
        int r = row0 + tid;
        if (r < M) {
            s_tok[tid] = g_tok[e * B_TOK + r];
            s_w[tid]   = g_w  [e * B_TOK + r];
        } else {
            s_tok[tid] = 0;
            s_w[tid]   = 0.0f;
        }
    }
    __syncthreads();

    const __nv_bfloat16* WeTh = g_WeT_hi + (size_t)e * H_DIM * H_DIM;
    const __nv_bfloat16* WeTl = g_WeT_lo + (size_t)e * H_DIM * H_DIM;

    // per-thread load slots: one 16B chunk per tensor per stage
    int lr = tid >> 2;          // 0..127 (row)
    int lc = tid & 3;           // 0..3   (16B chunk within 64B of k-tile)
    uint32_t s_off = (uint32_t)(lr * (KTP * 2) + lc * 16);
    size_t   a_go  = (size_t)s_tok[lr] * H_DIM + lc * 8;
    size_t   b_go  = (size_t)(col0 + lr) * H_DIM + lc * 8;

    // issue loads for k-tile t into stage st
    auto load_stage = [&](int t, int st) {
        uint32_t sb = sbase + st * STAGE_B + s_off;
        int k0 = t * KT;
        CP_ASYNC16(sb + 0 * TENSOR_B, (const char*)(g_x_hi + a_go + k0));
        CP_ASYNC16(sb + 1 * TENSOR_B, (const char*)(g_x_lo + a_go + k0));
        CP_ASYNC16(sb + 2 * TENSOR_B, (const char*)(WeTh + b_go + k0));
        CP_ASYNC16(sb + 3 * TENSOR_B, (const char*)(WeTl + b_go + k0));
        CP_COMMIT();
    };

    float acc[2][4][4];
#pragma unroll
    for (int mi = 0; mi < 2; mi++)
#pragma unroll
        for (int ni = 0; ni < 4; ni++)
#pragma unroll
            for (int j = 0; j < 4; j++) acc[mi][ni][j] = 0.0f;

    // ldmatrix lane-address components
    int aRow = (lane & 7) + ((lane >> 3) & 1) * 8;  // A: tiles {m, m+8, k, k+8}
    int aKb  = ((lane >> 4) & 1) * 16;
    int bRow = (lane & 7) + ((lane >> 4) & 1) * 8;  // B: tiles {k, k+8, n+8...}
    int bKb  = ((lane >> 3) & 1) * 16;

    load_stage(0, 0);

    for (int t = 0; t < N_KTILES; t++) {
        int st = t & 1;
        if (t + 1 < N_KTILES) {
            load_stage(t + 1, st ^ 1);
            CP_WAIT(1);
        } else {
            CP_WAIT(0);
        }
        __syncthreads();

        uint32_t sA = sbase + st * STAGE_B;
        uint32_t sB = sA + 2 * TENSOR_B;

#pragma unroll
        for (int ks = 0; ks < 2; ks++) {
            int kb = ks * 32;  // 16 elems * 2B
            uint32_t ah[2][4], al[2][4], bh[2][4], bl[2][4];
#pragma unroll
            for (int mi = 0; mi < 2; mi++) {
                uint32_t ra = (uint32_t)((wm * 32 + mi * 16 + aRow) * (KTP * 2) + kb + aKb);
                ldm4(ah[mi], sA + 0 * TENSOR_B + ra);
                ldm4(al[mi], sA + 1 * TENSOR_B + ra);
            }
#pragma unroll
            for (int np = 0; np < 2; np++) {
                uint32_t rb = (uint32_t)((wn * 32 + np * 16 + bRow) * (KTP * 2) + kb + bKb);
                ldm4(bh[np], sB + 0 * TENSOR_B + rb);
                ldm4(bl[np], sB + 1 * TENSOR_B + rb);
            }
#pragma unroll
            for (int mi = 0; mi < 2; mi++) {
#pragma unroll
                for (int ni = 0; ni < 4; ni++) {
                    uint32_t b0h = bh[ni >> 1][(ni & 1) * 2];
                    uint32_t b1h = bh[ni >> 1][(ni & 1) * 2 + 1];
                    uint32_t b0l = bl[ni >> 1][(ni & 1) * 2];
                    uint32_t b1l = bl[ni >> 1][(ni & 1) * 2 + 1];
                    mma16816(acc[mi][ni], ah[mi], b0h, b1h);
                    mma16816(acc[mi][ni], ah[mi], b0l, b1l);
                    mma16816(acc[mi][ni], al[mi], b0h, b1h);
                }
            }
        }
        __syncthreads();
    }

    // epilogue: weighted atomic scatter-add with bias
    const float* bep = be + (size_t)e * H_DIM + col0 + wn * 32;
#pragma unroll
    for (int mi = 0; mi < 2; mi++) {
        int g = wm * 32 + mi * 16 + (lane >> 2);
#pragma unroll
        for (int h = 0; h < 2; h++) {
            int rr = g + h * 8;
            if (row0 + rr < M) {
                float w   = s_w[rr];
                float* op = out + (size_t)s_tok[rr] * H_DIM + col0 + wn * 32;
#pragma unroll
                for (int ni = 0; ni < 4; ni++) {
                    int c = ni * 8 + (lane & 3) * 2;
                    float b0 = __ldg(bep + c);
                    float b1 = __ldg(bep + c + 1);
                    atomicAdd(op + c,     w * (acc[mi][ni][h * 2]     + b0));
                    atomicAdd(op + c + 1, w * (acc[mi][ni][h * 2 + 1] + b1));
                }
            }
        }
    }
}

// ---------------------------------------------------------------------------
// launch
// ---------------------------------------------------------------------------
extern "C" void kernel_launch(void* const* d_in, const int* in_sizes, int n_in,
                              void* d_out, int out_size) {
    const float* x  = (const float*)d_in[0];   // [B, H]
    const float* Wg = (const float*)d_in[1];   // [H, E]
    const float* bg = (const float*)d_in[2];   // [E]
    const float* We = (const float*)d_in[3];   // [E, H, H]
    const float* be = (const float*)d_in[4];   // [E, H]
    float* out = (float*)d_out;                // [B, H]

    cudaFuncSetAttribute(moe_mma_kernel,
                         cudaFuncAttributeMaxDynamicSharedMemorySize, DSMEM_BYTES);

    init_kernel<<<1024, 256>>>(out, out_size);
    conv_x_kernel<<<4096, 256>>>(x);
    {
        dim3 grid(H_DIM / 32, H_DIM / 32, N_EXP);
        conv_weT_kernel<<<grid, dim3(32, 8)>>>(We);
    }
    gate_kernel<<<B_TOK / 8, 256>>>(x, Wg, bg);

    dim3 grid(H_DIM / BN, B_TOK / BM, N_EXP);
    moe_mma_kernel<<<grid, 512, DSMEM_BYTES>>>(be, out);
}